// round 15
// baseline (speedup 1.0000x reference)
#include <cuda_runtime.h>
#include <cstdint>

#define VS 100
#define BATCH 8
#define NUM_COORDS 65536
#define NPTS (BATCH * NUM_COORDS)          // 524288
#define NCELLS (BATCH * VS * VS * VS)      // 8,000,000

#define GROUPS 5                            // cells per block = GROUPS*256 = 1280
#define CPB (GROUPS * 256)
#define NBLK (NCELLS / CPB)                 // 6250, exact

// Scratch: zero-initialized at module load; finalize re-zeroes exactly the
// occupied cells it consumes -> graph replays deterministic, no clear pass.
// g_sum ch0..5 = sums(x,y,z,f0,f1,f2), ch6 = count, ch7 = 0.
__device__ float g_sum[(size_t)NCELLS * 8];   // 256 MB
__device__ unsigned char g_flag[NCELLS];      // 8 MB occupancy flags

__global__ void __launch_bounds__(256) scatter_kernel(
    const float* __restrict__ coords,
    const float* __restrict__ feats)
{
    int idx = blockIdx.x * blockDim.x + threadIdx.x;
    if (idx >= NPTS) return;

    float x = coords[idx * 3 + 0];
    float y = coords[idx * 3 + 1];
    float z = coords[idx * 3 + 2];

    // Reference constants collapse in f32: res = denom = 0.01f, shift = -0.01f
    const float shift = 0.01f;
    const float denom = 0.01f;
    int ix = (int)floorf((x + shift) / denom);
    int iy = (int)floorf((y + shift) / denom);
    int iz = (int)floorf((z + shift) / denom);

    if (ix < 1 || ix > VS || iy < 1 || iy > VS || iz < 1 || iz > VS) return;

    int b = idx >> 16;  // NUM_COORDS = 65536
    int cell = ((b * VS + (ix - 1)) * VS + (iy - 1)) * VS + (iz - 1);

    float f0 = feats[idx * 3 + 0];
    float f1 = feats[idx * 3 + 1];
    float f2 = feats[idx * 3 + 2];

    float* s = &g_sum[(size_t)cell * 8];
    // Two v4 return-less reductions per point; count folded into ch6.
    asm volatile("red.global.add.v4.f32 [%0], {%1, %2, %3, %4};"
                 :: "l"(s), "f"(x), "f"(y), "f"(z), "f"(f0) : "memory");
    asm volatile("red.global.add.v4.f32 [%0], {%1, %2, %3, %4};"
                 :: "l"(s + 4), "f"(f1), "f"(f2), "f"(1.0f), "f"(0.0f) : "memory");
    // Benign-race occupancy flag (all writers store 1).
    g_flag[cell] = 1;
}

__global__ void __launch_bounds__(256) finalize_kernel(float* __restrict__ out)
{
    __shared__ __align__(16) float stage[2][2560];  // 2 x 10 KB double buffer

    int blockBase = blockIdx.x * CPB;

    // Prefetch all groups' flags up front (5 coalesced independent loads).
    unsigned char fl[GROUPS];
#pragma unroll
    for (int g = 0; g < GROUPS; g++) {
        fl[g] = g_flag[blockBase + g * 256 + threadIdx.x];
    }

    // Software pipeline: sums for group g are issued during group g-1.
    float4 z4 = make_float4(0.f, 0.f, 0.f, 0.f);
    float4 a_pf = z4, b_pf = z4;
    {
        float4* sp0 = (float4*)&g_sum[(size_t)(blockBase + threadIdx.x) * 8];
        if (fl[0]) { a_pf = sp0[0]; b_pf = sp0[1]; }
    }

#pragma unroll
    for (int g = 0; g < GROUPS; g++) {
        int buf = g & 1;
        int cell = blockBase + g * 256 + threadIdx.x;

        // Consume this group's prefetched sums.
        float4 a = a_pf;
        float4 b4 = b_pf;

        // Issue next group's sum loads immediately (overlaps this group's
        // staging + TMA work).
        if (g + 1 < GROUPS) {
            a_pf = z4;
            b_pf = z4;
            float4* spn = (float4*)&g_sum[(size_t)(cell + 256) * 8];
            if (fl[g + 1]) { a_pf = spn[0]; b_pf = spn[1]; }
        }

        // Decode (i, j, k) within the batch's 100^3 block.
        int k = cell % VS;
        int t = cell / VS;
        int j = t % VS;
        int i = (t / VS) % VS;

        float v0 = 0.f, v1 = 0.f, v2 = 0.f, v3 = 0.f, v4 = 0.f, v5 = 0.f;
        float occ = 0.f;
        if (fl[g]) {
            float cnt = b4.z;  // count accumulated in ch6
            v0 = a.x / cnt;
            v1 = a.y / cnt;
            v2 = a.z / cnt;
            v3 = a.w / cnt;
            v4 = b4.x / cnt;
            v5 = b4.y / cnt;
            occ = 1.0f;
            // Self-clean scratch for the next graph replay.
            float4* sp = (float4*)&g_sum[(size_t)cell * 8];
            sp[0] = z4;
            sp[1] = z4;
            g_flag[cell] = 0;
        }

        // Drain the store issued on this buffer two groups ago before reuse.
        if (g >= 2) {
            if (threadIdx.x == 0) {
                asm volatile("cp.async.bulk.wait_group 1;" ::: "memory");
            }
            __syncthreads();
        }

        float* st = stage[buf] + threadIdx.x * 10;
        st[0] = v0;
        st[1] = v1;
        st[2] = v2;
        st[3] = v3;
        st[4] = v4;
        st[5] = v5;
        st[6] = (float)i * 0.01f;
        st[7] = (float)j * 0.01f;
        st[8] = (float)k * 0.01f;
        st[9] = occ;
        __syncthreads();

        if (threadIdx.x == 0) {
            uint32_t smem_addr = (uint32_t)__cvta_generic_to_shared(stage[buf]);
            float* dst = out + (size_t)(blockBase + g * 256) * 10;
            asm volatile("fence.proxy.async.shared::cta;" ::: "memory");
            asm volatile("cp.async.bulk.global.shared::cta.bulk_group [%0], [%1], %2;"
                         :: "l"(dst), "r"(smem_addr), "r"(10240) : "memory");
            asm volatile("cp.async.bulk.commit_group;" ::: "memory");
        }
    }

    // Keep the CTA (and its smem) alive until all stores drain.
    if (threadIdx.x == 0) {
        asm volatile("cp.async.bulk.wait_group 0;" ::: "memory");
    }
}

extern "C" void kernel_launch(void* const* d_in, const int* in_sizes, int n_in,
                              void* d_out, int out_size)
{
    const float* coords = (const float*)d_in[0];
    const float* feats  = (const float*)d_in[1];
    float* out = (float*)d_out;

    scatter_kernel<<<(NPTS + 255) / 256, 256>>>(coords, feats);
    finalize_kernel<<<NBLK, 256>>>(out);  // 6250 blocks x 1280 cells
}

// round 17
// speedup vs baseline: 1.1358x; 1.1358x over previous
#include <cuda_runtime.h>
#include <cstdint>

#define VS 100
#define BATCH 8
#define NUM_COORDS 65536
#define NPTS (BATCH * NUM_COORDS)          // 524288
#define NCELLS (BATCH * VS * VS * VS)      // 8,000,000

#define GROUPS 5                            // cells per block = GROUPS*256 = 1280
#define CPB (GROUPS * 256)
#define NBLK (NCELLS / CPB)                 // 6250, exact

// Scratch: zero-initialized at module load; finalize re-zeroes exactly the
// occupied cells it consumes -> graph replays deterministic, no clear pass.
// g_sum ch0..5 = sums(x,y,z,f0,f1,f2), ch6 = count, ch7 = 0.
__device__ float g_sum[(size_t)NCELLS * 8];   // 256 MB
__device__ unsigned char g_flag[NCELLS];      // 8 MB occupancy flags

__global__ void __launch_bounds__(256) scatter_kernel(
    const float* __restrict__ coords,
    const float* __restrict__ feats)
{
    int idx = blockIdx.x * blockDim.x + threadIdx.x;
    if (idx >= NPTS) return;

    float x = coords[idx * 3 + 0];
    float y = coords[idx * 3 + 1];
    float z = coords[idx * 3 + 2];

    // Reference constants collapse in f32: res = denom = 0.01f, shift = -0.01f
    const float shift = 0.01f;
    const float denom = 0.01f;
    int ix = (int)floorf((x + shift) / denom);
    int iy = (int)floorf((y + shift) / denom);
    int iz = (int)floorf((z + shift) / denom);

    if (ix < 1 || ix > VS || iy < 1 || iy > VS || iz < 1 || iz > VS) return;

    int b = idx >> 16;  // NUM_COORDS = 65536
    int cell = ((b * VS + (ix - 1)) * VS + (iy - 1)) * VS + (iz - 1);

    float f0 = feats[idx * 3 + 0];
    float f1 = feats[idx * 3 + 1];
    float f2 = feats[idx * 3 + 2];

    float* s = &g_sum[(size_t)cell * 8];
    // Two v4 return-less reductions per point; count folded into ch6.
    asm volatile("red.global.add.v4.f32 [%0], {%1, %2, %3, %4};"
                 :: "l"(s), "f"(x), "f"(y), "f"(z), "f"(f0) : "memory");
    asm volatile("red.global.add.v4.f32 [%0], {%1, %2, %3, %4};"
                 :: "l"(s + 4), "f"(f1), "f"(f2), "f"(1.0f), "f"(0.0f) : "memory");
    // Benign-race occupancy flag (all writers store 1).
    g_flag[cell] = 1;
}

__global__ void __launch_bounds__(256) finalize_kernel(float* __restrict__ out)
{
    __shared__ __align__(16) float stage[2][2560];     // 20 KB output staging
    __shared__ __align__(16) float sums[2][256][8];    // 16 KB cp.async landing

    int blockBase = blockIdx.x * CPB;

    // Prefetch all groups' flags (5 coalesced independent byte loads).
    unsigned char fl[GROUPS];
#pragma unroll
    for (int g = 0; g < GROUPS; g++) {
        fl[g] = g_flag[blockBase + g * 256 + threadIdx.x];
    }

    // Issue group g's 32B of sums into sums[g&1][tid] via cp.async.
    // Predicated by flag through src_size: 0 -> zero-fill, no gmem read.
    uint32_t my0 = (uint32_t)__cvta_generic_to_shared(&sums[0][threadIdx.x][0]);
    uint32_t my1 = (uint32_t)__cvta_generic_to_shared(&sums[1][threadIdx.x][0]);

#define ISSUE_SUMS(g)                                                          \
    do {                                                                       \
        const float* _src = &g_sum[(size_t)(blockBase + (g) * 256 + threadIdx.x) * 8]; \
        uint32_t _dst = ((g) & 1) ? my1 : my0;                                 \
        int _sz = fl[(g)] ? 16 : 0;                                            \
        asm volatile("cp.async.cg.shared.global [%0], [%1], 16, %2;"           \
                     :: "r"(_dst), "l"(_src), "r"(_sz) : "memory");            \
        asm volatile("cp.async.cg.shared.global [%0], [%1], 16, %2;"           \
                     :: "r"(_dst + 16), "l"(_src + 4), "r"(_sz) : "memory");   \
        asm volatile("cp.async.commit_group;" ::: "memory");                   \
    } while (0)

    ISSUE_SUMS(0);
    ISSUE_SUMS(1);

#pragma unroll
    for (int g = 0; g < GROUPS; g++) {
        int buf = g & 1;
        int cell = blockBase + g * 256 + threadIdx.x;

        // Wait for this group's copies. At g < GROUPS-1 exactly one newer
        // group is in flight; at the LAST group none are newer, so we must
        // wait_group 0 (R16's NaN bug: wait_group 1 let group 4 stay pending).
        if (g == GROUPS - 1) {
            asm volatile("cp.async.wait_group 0;" ::: "memory");
        } else {
            asm volatile("cp.async.wait_group 1;" ::: "memory");
        }
        float4 a  = *(float4*)&sums[buf][threadIdx.x][0];
        float4 b4 = *(float4*)&sums[buf][threadIdx.x][4];

        // Refill this buffer for group g+2 (slot already consumed).
        if (g + 2 < GROUPS) ISSUE_SUMS(g + 2);

        // Decode (i, j, k) within the batch's 100^3 block.
        int k = cell % VS;
        int t = cell / VS;
        int j = t % VS;
        int i = (t / VS) % VS;

        float v0 = 0.f, v1 = 0.f, v2 = 0.f, v3 = 0.f, v4 = 0.f, v5 = 0.f;
        float occ = 0.f;
        if (fl[g]) {
            float cnt = b4.z;  // count accumulated in ch6
            v0 = a.x / cnt;
            v1 = a.y / cnt;
            v2 = a.z / cnt;
            v3 = a.w / cnt;
            v4 = b4.x / cnt;
            v5 = b4.y / cnt;
            occ = 1.0f;
            // Self-clean scratch for the next graph replay.
            float4 z4 = make_float4(0.f, 0.f, 0.f, 0.f);
            float4* sp = (float4*)&g_sum[(size_t)cell * 8];
            sp[0] = z4;
            sp[1] = z4;
            g_flag[cell] = 0;
        }

        // Drain the TMA store issued on this stage buffer two groups ago.
        if (g >= 2) {
            if (threadIdx.x == 0) {
                asm volatile("cp.async.bulk.wait_group 1;" ::: "memory");
            }
            __syncthreads();
        }

        float* st = stage[buf] + threadIdx.x * 10;
        st[0] = v0;
        st[1] = v1;
        st[2] = v2;
        st[3] = v3;
        st[4] = v4;
        st[5] = v5;
        st[6] = (float)i * 0.01f;
        st[7] = (float)j * 0.01f;
        st[8] = (float)k * 0.01f;
        st[9] = occ;
        __syncthreads();

        if (threadIdx.x == 0) {
            uint32_t smem_addr = (uint32_t)__cvta_generic_to_shared(stage[buf]);
            float* dst = out + (size_t)(blockBase + g * 256) * 10;
            asm volatile("fence.proxy.async.shared::cta;" ::: "memory");
            asm volatile("cp.async.bulk.global.shared::cta.bulk_group [%0], [%1], %2;"
                         :: "l"(dst), "r"(smem_addr), "r"(10240) : "memory");
            asm volatile("cp.async.bulk.commit_group;" ::: "memory");
        }
    }

    // Keep the CTA (and its smem) alive until all bulk stores drain.
    if (threadIdx.x == 0) {
        asm volatile("cp.async.bulk.wait_group 0;" ::: "memory");
    }
#undef ISSUE_SUMS
}

extern "C" void kernel_launch(void* const* d_in, const int* in_sizes, int n_in,
                              void* d_out, int out_size)
{
    const float* coords = (const float*)d_in[0];
    const float* feats  = (const float*)d_in[1];
    float* out = (float*)d_out;

    scatter_kernel<<<(NPTS + 255) / 256, 256>>>(coords, feats);
    finalize_kernel<<<NBLK, 256>>>(out);  // 6250 blocks x 1280 cells
}